// round 2
// baseline (speedup 1.0000x reference)
#include <cuda_runtime.h>
#include <cuda_bf16.h>

// Scratch (allocation-free rule: __device__ globals)
__device__ float g_qkvT[32ll * 768 * 1024];    //  96 MB: Q^T/K^T/V^T per (b,c), layout (bc, e, t)
__device__ float g_scores[32ll * 1024 * 1024]; // 128 MB: attention scores / probs
__device__ float g_attnO[32ll * 1024 * 256];   //  32 MB: attention output (bc, q, d)

#define BM 128
#define BN 128
#define BK 8

// Generic 128x128x8 SGEMM, 256 threads, 8x8 per-thread tile.
// A_KC: element (m,k) contiguous in k (sa_k==1).  else contiguous in m (sa_m==1).
// B_KC: element (n,k) contiguous in k (sb_k==1).  else contiguous in n (sb_n==1).
// C row-major (m,n) with ldc. Optional per-m bias, per-n bias, int mask (!=0 -> -inf).
template<bool A_KC, bool B_KC>
__global__ __launch_bounds__(256) void gemm_kernel(
    const float* __restrict__ A, const float* __restrict__ B, float* __restrict__ C,
    int M, int N, int K,
    long long strideA, long long strideB, long long strideC,
    int sa_m, int sa_k, int sb_n, int sb_k, int ldc,
    float alpha,
    const float* __restrict__ bias_m, const float* __restrict__ bias_n,
    const int* __restrict__ maskp, long long strideMask, int maskRow)
{
    __shared__ float As[BK][BM];
    __shared__ float Bs[BK][BN];

    const int bz = blockIdx.z;
    A += (long long)bz * strideA;
    B += (long long)bz * strideB;
    C += (long long)bz * strideC;
    const int* mk = maskp ? (maskp + (long long)bz * strideMask) : nullptr;

    const int tid = threadIdx.x;
    const int m0 = blockIdx.y * BM;
    const int n0 = blockIdx.x * BN;
    const int tx = tid & 15;   // n sub-tile
    const int ty = tid >> 4;   // m sub-tile

    float acc[8][8];
#pragma unroll
    for (int i = 0; i < 8; i++)
#pragma unroll
        for (int j = 0; j < 8; j++) acc[i][j] = 0.f;

    for (int k0 = 0; k0 < K; k0 += BK) {
        // ---- load A tile into As[k][m] ----
        if (A_KC) {
            int mm = tid >> 1;
            int kk = (tid & 1) * 4;
            float4 v = *reinterpret_cast<const float4*>(
                &A[(long long)(m0 + mm) * sa_m + (k0 + kk)]);
            As[kk + 0][mm] = v.x; As[kk + 1][mm] = v.y;
            As[kk + 2][mm] = v.z; As[kk + 3][mm] = v.w;
        } else {
            int mm = tid & 127;
            int kb = tid >> 7;
#pragma unroll
            for (int u = 0; u < 4; u++) {
                int kk = kb + u * 2;
                As[kk][mm] = A[(long long)(k0 + kk) * sa_k + (m0 + mm)];
            }
        }
        // ---- load B tile into Bs[k][n] ----
        if (B_KC) {
            int nn = tid >> 1;
            int kk = (tid & 1) * 4;
            float4 v = *reinterpret_cast<const float4*>(
                &B[(long long)(n0 + nn) * sb_n + (k0 + kk)]);
            Bs[kk + 0][nn] = v.x; Bs[kk + 1][nn] = v.y;
            Bs[kk + 2][nn] = v.z; Bs[kk + 3][nn] = v.w;
        } else {
            int nn = tid & 127;
            int kb = tid >> 7;
#pragma unroll
            for (int u = 0; u < 4; u++) {
                int kk = kb + u * 2;
                Bs[kk][nn] = B[(long long)(k0 + kk) * sb_k + (n0 + nn)];
            }
        }
        __syncthreads();

#pragma unroll
        for (int kk = 0; kk < BK; kk++) {
            float a[8], b[8];
#pragma unroll
            for (int i = 0; i < 8; i++) a[i] = As[kk][ty * 8 + i];
#pragma unroll
            for (int j = 0; j < 8; j++) b[j] = Bs[kk][tx * 8 + j];
#pragma unroll
            for (int i = 0; i < 8; i++)
#pragma unroll
                for (int j = 0; j < 8; j++)
                    acc[i][j] += a[i] * b[j];
        }
        __syncthreads();
    }

    const float NEG_INF = __int_as_float(0xff800000);
    float bn[8];
#pragma unroll
    for (int j = 0; j < 8; j++) bn[j] = bias_n ? bias_n[n0 + tx * 8 + j] : 0.f;

#pragma unroll
    for (int i = 0; i < 8; i++) {
        int row = m0 + ty * 8 + i;
        float bm = bias_m ? bias_m[row] : 0.f;
#pragma unroll
        for (int j = 0; j < 8; j++) {
            int col = n0 + tx * 8 + j;
            float v = acc[i][j] * alpha + bm + bn[j];
            if (mk && mk[(long long)row * maskRow + col] != 0) v = NEG_INF;
            C[(long long)row * ldc + col] = v;
        }
    }
}

// Row softmax over length-1024 rows. One block (256 threads, float4 each) per row.
__global__ __launch_bounds__(256) void softmax_kernel(float* __restrict__ S)
{
    const long long row = blockIdx.x;
    float* p = S + row * 1024;
    const int tid = threadIdx.x;

    float4 v = reinterpret_cast<float4*>(p)[tid];

    float m = fmaxf(fmaxf(v.x, v.y), fmaxf(v.z, v.w));
#pragma unroll
    for (int o = 16; o; o >>= 1) m = fmaxf(m, __shfl_xor_sync(0xffffffffu, m, o));

    __shared__ float red[8];
    if ((tid & 31) == 0) red[tid >> 5] = m;
    __syncthreads();
    float mm = red[0];
#pragma unroll
    for (int w = 1; w < 8; w++) mm = fmaxf(mm, red[w]);
    __syncthreads();

    float e0 = (v.x <= -1e30f) ? 0.f : __expf(v.x - mm);
    float e1 = (v.y <= -1e30f) ? 0.f : __expf(v.y - mm);
    float e2 = (v.z <= -1e30f) ? 0.f : __expf(v.z - mm);
    float e3 = (v.w <= -1e30f) ? 0.f : __expf(v.w - mm);

    float s = e0 + e1 + e2 + e3;
#pragma unroll
    for (int o = 16; o; o >>= 1) s += __shfl_xor_sync(0xffffffffu, s, o);
    if ((tid & 31) == 0) red[tid >> 5] = s;
    __syncthreads();
    float tot = red[0];
#pragma unroll
    for (int w = 1; w < 8; w++) tot += red[w];

    float inv = 1.0f / tot;
    float4 o4 = make_float4(e0 * inv, e1 * inv, e2 * inv, e3 * inv);
    reinterpret_cast<float4*>(p)[tid] = o4;
}

extern "C" void kernel_launch(void* const* d_in, const int* in_sizes, int n_in,
                              void* d_out, int out_size)
{
    const float* x     = (const float*)d_in[0];   // (8,4,256,1024)
    const int*   mask  = (const int*)d_in[1];     // (8,4,1024,1024) bool -> 4-byte
    const float* w_qkv = (const float*)d_in[2];   // (768,256)
    const float* b_qkv = (const float*)d_in[3];   // (768,)
    const float* w_out = (const float*)d_in[4];   // (256,256)
    const float* b_out = (const float*)d_in[5];   // (256,)
    float*       out   = (float*)d_out;           // (8,4,1024,256)

    float *qkvT, *scores, *attnO;
    cudaGetSymbolAddress((void**)&qkvT,   g_qkvT);
    cudaGetSymbolAddress((void**)&scores, g_scores);
    cudaGetSymbolAddress((void**)&attnO,  g_attnO);

    const dim3 blk(256);
    const long long QKV_BC = 768ll * 1024;   // per-bc stride of qkvT
    const long long SC_BC  = 1024ll * 1024;  // per-bc stride of scores / mask
    const long long O_BC   = 1024ll * 256;   // per-bc stride of attnO / out

    // 1) QKV^T[bc](e,t) = w_qkv(e,d) @ x[bc](d,t) + b_qkv[e]
    gemm_kernel<true, false><<<dim3(1024 / BN, 768 / BM, 32), blk>>>(
        w_qkv, x, qkvT, 768, 1024, 256,
        0, 256ll * 1024, QKV_BC,
        /*sa_m*/256, /*sa_k*/1, /*sb_n*/1, /*sb_k*/1024, /*ldc*/1024,
        1.0f, b_qkv, nullptr, nullptr, 0, 0);

    // 2) scores[bc](q,k) = scale * Q @ K^T, then mask -> -inf
    gemm_kernel<false, false><<<dim3(1024 / BN, 1024 / BM, 32), blk>>>(
        qkvT /*Q block*/, qkvT + 256ll * 1024 /*K block*/, scores,
        1024, 1024, 256,
        QKV_BC, QKV_BC, SC_BC,
        /*sa_m*/1, /*sa_k*/1024, /*sb_n*/1, /*sb_k*/1024, /*ldc*/1024,
        0.0625f /*1/sqrt(256)*/, nullptr, nullptr,
        mask, SC_BC, 1024);

    // 3) row softmax over 32*1024 rows of length 1024
    softmax_kernel<<<32 * 1024, blk>>>(scores);

    // 4) attnO[bc](q,d) = P(q,k) @ V
    gemm_kernel<true, true><<<dim3(256 / BN, 1024 / BM, 32), blk>>>(
        scores, qkvT + 512ll * 1024, attnO,
        1024, 256, 1024,
        SC_BC, QKV_BC, O_BC,
        /*sa_m*/1024, /*sa_k*/1, /*sb_n*/1024, /*sb_k*/1, /*ldc*/256,
        1.0f, nullptr, nullptr, nullptr, 0, 0);

    // 5) out[bc](q,e) = attnO(q,d) @ w_out(e,d)^T + b_out[e]
    gemm_kernel<true, true><<<dim3(256 / BN, 1024 / BM, 32), blk>>>(
        attnO, w_out, out,
        1024, 256, 256,
        O_BC, 0, O_BC,
        /*sa_m*/256, /*sa_k*/1, /*sb_n*/256, /*sb_k*/1, /*ldc*/256,
        1.0f, nullptr, b_out, nullptr, 0, 0);
}

// round 4
// speedup vs baseline: 2.7448x; 2.7448x over previous
#include <cuda_runtime.h>
#include <cuda_fp16.h>
#include <cstdint>

// ---------------- scratch (__device__ globals; no allocs allowed) ----------------
__device__ float g_xt[32ll * 1024 * 256];      // x transposed: (bc, t, d)
__device__ float g_qk[32ll * 1024 * 512];      // Q,K: (bc, t, 512)
__device__ float g_vt[32ll * 256 * 1024];      // V^T: (bc, d, t)
__device__ float g_scores[32ll * 1024 * 1024]; // scores / probs
__device__ float g_attnO[32ll * 1024 * 256];   // attention out

__device__ __forceinline__ uint32_t smem_u32(const void* p) {
    uint32_t a;
    asm("{ .reg .u64 t; cvta.to.shared.u64 t, %1; cvt.u32.u64 %0, t; }" : "=r"(a) : "l"(p));
    return a;
}

#define LDSM4(r0, r1, r2, r3, addr)                                               \
    asm volatile("ldmatrix.sync.aligned.m8n8.x4.shared.b16 {%0,%1,%2,%3}, [%4];"  \
                 : "=r"(r0), "=r"(r1), "=r"(r2), "=r"(r3) : "r"(addr))

#define MMA16816(c, a, b0, b1)                                                    \
    asm volatile("mma.sync.aligned.m16n8k16.row.col.f32.f16.f16.f32 "             \
                 "{%0,%1,%2,%3},{%4,%5,%6,%7},{%8,%9},{%0,%1,%2,%3};"             \
                 : "+f"((c)[0]), "+f"((c)[1]), "+f"((c)[2]), "+f"((c)[3])         \
                 : "r"((a)[0]), "r"((a)[1]), "r"((a)[2]), "r"((a)[3]),            \
                   "r"(b0), "r"(b1))

// SMEM tile layout: 128 rows x 32 halves, padded to 40 halves (80 B) per row.
#define PITCHB   80
#define TILE_B   (128 * PITCHB)            // 10240 B
#define OFF_AH   0
#define OFF_AL   TILE_B
#define OFF_BH   (2 * TILE_B)
#define OFF_BL   (3 * TILE_B)
#define BUF_B    (4 * TILE_B)              // 40960 B per stage
#define SMEM_BYTES (2 * BUF_B)             // 81920 B

// float4 -> fp16 hi/lo pairs (each as 2x half2 packed in uint2)
__device__ __forceinline__ void cvt4(float4 v, uint2& h, uint2& l) {
    __half2 h01 = __floats2half2_rn(v.x, v.y);
    __half2 h23 = __floats2half2_rn(v.z, v.w);
    float2 f01 = __half22float2(h01);
    float2 f23 = __half22float2(h23);
    __half2 l01 = __floats2half2_rn(v.x - f01.x, v.y - f01.y);
    __half2 l23 = __floats2half2_rn(v.z - f23.x, v.w - f23.y);
    h.x = *reinterpret_cast<uint32_t*>(&h01);
    h.y = *reinterpret_cast<uint32_t*>(&h23);
    l.x = *reinterpret_cast<uint32_t*>(&l01);
    l.y = *reinterpret_cast<uint32_t*>(&l23);
}

// C[128 x 128 tile] = A(m,k) . B(n,k)^T with fp32-equivalent accuracy.
// A: lda k-contiguous rows. B: ldb k-contiguous rows. C row-major ldc.
// qkv_mode: output cols >= 512 go transposed into VT instead of C.
__global__ __launch_bounds__(256) void hgemm(
    const float* __restrict__ A, const float* __restrict__ B,
    float* __restrict__ C, float* __restrict__ VT,
    int K, int lda, int ldb, int ldc,
    long long sA, long long sB, long long sC,
    float alpha, const float* __restrict__ bias_n,
    const int* __restrict__ maskp, long long sMask, int qkv_mode)
{
    extern __shared__ char smem[];
    const uint32_t sbase = smem_u32(smem);
    const int tid = threadIdx.x;
    const int wid = tid >> 5, lane = tid & 31;
    const int bz = blockIdx.z;
    const int n0 = blockIdx.x * 128, m0 = blockIdx.y * 128;
    const int warp_m = wid & 1, warp_n = wid >> 1;   // 2 x 4 warp grid

    const float* Ab = A + bz * sA + (long long)m0 * lda;
    const float* Bb = B + bz * sB + (long long)n0 * ldb;

    float acc[4][4][4];
#pragma unroll
    for (int mt = 0; mt < 4; mt++)
#pragma unroll
        for (int nt = 0; nt < 4; nt++)
#pragma unroll
            for (int r = 0; r < 4; r++) acc[mt][nt][r] = 0.f;

    // global staging registers
    float4 ra[4], rb[4];
    const int ldr = tid >> 3;        // row handled by this thread (base)
    const int ldc4 = tid & 7;        // float4 column

    auto LOAD = [&](int k0) {
#pragma unroll
        for (int i = 0; i < 4; i++) {
            int r = ldr + i * 32;
            ra[i] = *reinterpret_cast<const float4*>(Ab + (long long)r * lda + k0 + ldc4 * 4);
            rb[i] = *reinterpret_cast<const float4*>(Bb + (long long)r * ldb + k0 + ldc4 * 4);
        }
    };
    auto STORE = [&](int buf) {
        char* base = smem + buf * BUF_B;
#pragma unroll
        for (int i = 0; i < 4; i++) {
            int r = ldr + i * 32;
            uint32_t off = (uint32_t)(r * PITCHB + ldc4 * 8);
            uint2 h, l;
            cvt4(ra[i], h, l);
            *reinterpret_cast<uint2*>(base + OFF_AH + off) = h;
            *reinterpret_cast<uint2*>(base + OFF_AL + off) = l;
            cvt4(rb[i], h, l);
            *reinterpret_cast<uint2*>(base + OFF_BH + off) = h;
            *reinterpret_cast<uint2*>(base + OFF_BL + off) = l;
        }
    };

    // lane-derived ldmatrix row/col offsets
    const int a_row = warp_m * 64 + (lane & 7) + ((lane >> 3) & 1) * 8;
    const int a_kq  = (lane >> 4) * 8;
    const int b_row = warp_n * 32 + (lane >> 4) * 8 + (lane & 7);
    const int b_kq  = ((lane >> 3) & 1) * 8;

    auto COMPUTE = [&](int buf) {
        const uint32_t o = sbase + buf * BUF_B;
#pragma unroll
        for (int s = 0; s < 2; s++) {
            uint32_t bh[8], bl[8];
#pragma unroll
            for (int p = 0; p < 2; p++) {
                uint32_t boff = (uint32_t)((b_row + p * 16) * PITCHB + (s * 16 + b_kq) * 2);
                LDSM4(bh[p * 4 + 0], bh[p * 4 + 1], bh[p * 4 + 2], bh[p * 4 + 3], o + OFF_BH + boff);
                LDSM4(bl[p * 4 + 0], bl[p * 4 + 1], bl[p * 4 + 2], bl[p * 4 + 3], o + OFF_BL + boff);
            }
#pragma unroll
            for (int mt = 0; mt < 4; mt++) {
                uint32_t ah[4], al[4];
                uint32_t aoff = (uint32_t)((a_row + mt * 16) * PITCHB + (s * 16 + a_kq) * 2);
                LDSM4(ah[0], ah[1], ah[2], ah[3], o + OFF_AH + aoff);
                LDSM4(al[0], al[1], al[2], al[3], o + OFF_AL + aoff);
#pragma unroll
                for (int nt = 0; nt < 4; nt++) {
                    const int i0 = (nt >> 1) * 4 + (nt & 1) * 2;
                    MMA16816(acc[mt][nt], ah, bh[i0], bh[i0 + 1]);
                    MMA16816(acc[mt][nt], ah, bl[i0], bl[i0 + 1]);
                    MMA16816(acc[mt][nt], al, bh[i0], bh[i0 + 1]);
                }
            }
        }
    };

    const int nch = K >> 5;
    LOAD(0);
    for (int ch = 0; ch < nch; ch++) {
        STORE(ch & 1);
        __syncthreads();
        if (ch + 1 < nch) LOAD((ch + 1) << 5);
        COMPUTE(ch & 1);
    }

    // ---------------- epilogue ----------------
    const float NEG_INF = __int_as_float(0xff800000);
    float* C_bz = C + bz * sC;
    float* VT_bz = VT ? (VT + bz * (256ll * 1024)) : nullptr;
    const int* mk = maskp ? (maskp + bz * sMask) : nullptr;
    const int gid = lane >> 2, q4 = lane & 3;

#pragma unroll
    for (int mt = 0; mt < 4; mt++) {
#pragma unroll
        for (int nt = 0; nt < 4; nt++) {
            const int col = n0 + warp_n * 32 + nt * 8 + q4 * 2;
            const int vmode = qkv_mode && (col >= 512);
            float b0 = 0.f, b1 = 0.f;
            if (bias_n) { b0 = bias_n[col]; b1 = bias_n[col + 1]; }
#pragma unroll
            for (int h = 0; h < 2; h++) {
                const int row = m0 + warp_m * 64 + mt * 16 + gid + h * 8;
                float v0 = acc[mt][nt][h * 2 + 0] * alpha + b0;
                float v1 = acc[mt][nt][h * 2 + 1] * alpha + b1;
                if (mk) {
                    int2 mv = *reinterpret_cast<const int2*>(mk + (long long)row * 1024 + col);
                    if (mv.x != 0) v0 = NEG_INF;
                    if (mv.y != 0) v1 = NEG_INF;
                }
                if (!vmode) {
                    *reinterpret_cast<float2*>(C_bz + (long long)row * ldc + col) =
                        make_float2(v0, v1);
                } else {
                    VT_bz[(long long)(col - 512) * 1024 + row] = v0;
                    VT_bz[(long long)(col - 511) * 1024 + row] = v1;
                }
            }
        }
    }
}

// ---------------- transpose x: (bc, 256, 1024) -> (bc, 1024, 256) ----------------
__global__ __launch_bounds__(256) void transpose_kernel(
    const float* __restrict__ x, float* __restrict__ xt)
{
    __shared__ float tile[32][33];
    const int bz = blockIdx.z;
    const float* xs = x + (long long)bz * 256 * 1024;
    float* xd = xt + (long long)bz * 1024 * 256;
    const int t0 = blockIdx.x * 32, d0 = blockIdx.y * 32;
    const int tx = threadIdx.x, ty = threadIdx.y;
#pragma unroll
    for (int k = 0; k < 4; k++)
        tile[ty + k * 8][tx] = xs[(long long)(d0 + ty + k * 8) * 1024 + t0 + tx];
    __syncthreads();
#pragma unroll
    for (int k = 0; k < 4; k++)
        xd[(long long)(t0 + ty + k * 8) * 256 + d0 + tx] = tile[tx][ty + k * 8];
}

// ---------------- row softmax over length-1024 rows ----------------
__global__ __launch_bounds__(256) void softmax_kernel(float* __restrict__ S)
{
    const long long row = blockIdx.x;
    float* p = S + row * 1024;
    const int tid = threadIdx.x;

    float4 v = reinterpret_cast<float4*>(p)[tid];
    float m = fmaxf(fmaxf(v.x, v.y), fmaxf(v.z, v.w));
#pragma unroll
    for (int o = 16; o; o >>= 1) m = fmaxf(m, __shfl_xor_sync(0xffffffffu, m, o));

    __shared__ float red[8];
    if ((tid & 31) == 0) red[tid >> 5] = m;
    __syncthreads();
    float mm = red[0];
#pragma unroll
    for (int w = 1; w < 8; w++) mm = fmaxf(mm, red[w]);
    __syncthreads();

    float e0 = (v.x <= -1e30f) ? 0.f : __expf(v.x - mm);
    float e1 = (v.y <= -1e30f) ? 0.f : __expf(v.y - mm);
    float e2 = (v.z <= -1e30f) ? 0.f : __expf(v.z - mm);
    float e3 = (v.w <= -1e30f) ? 0.f : __expf(v.w - mm);

    float s = e0 + e1 + e2 + e3;
#pragma unroll
    for (int o = 16; o; o >>= 1) s += __shfl_xor_sync(0xffffffffu, s, o);
    if ((tid & 31) == 0) red[tid >> 5] = s;
    __syncthreads();
    float tot = red[0];
#pragma unroll
    for (int w = 1; w < 8; w++) tot += red[w];

    float inv = 1.0f / tot;
    reinterpret_cast<float4*>(p)[tid] = make_float4(e0 * inv, e1 * inv, e2 * inv, e3 * inv);
}

extern "C" void kernel_launch(void* const* d_in, const int* in_sizes, int n_in,
                              void* d_out, int out_size)
{
    const float* x     = (const float*)d_in[0];   // (8,4,256,1024)
    const int*   mask  = (const int*)d_in[1];     // (8,4,1024,1024) bool -> int32
    const float* w_qkv = (const float*)d_in[2];   // (768,256)
    const float* b_qkv = (const float*)d_in[3];   // (768,)
    const float* w_out = (const float*)d_in[4];   // (256,256)
    const float* b_out = (const float*)d_in[5];   // (256,)
    float*       out   = (float*)d_out;           // (8,4,1024,256)

    float *xt, *qk, *vt, *scores, *attnO;
    cudaGetSymbolAddress((void**)&xt,     g_xt);
    cudaGetSymbolAddress((void**)&qk,     g_qk);
    cudaGetSymbolAddress((void**)&vt,     g_vt);
    cudaGetSymbolAddress((void**)&scores, g_scores);
    cudaGetSymbolAddress((void**)&attnO,  g_attnO);

    cudaFuncSetAttribute(hgemm, cudaFuncAttributeMaxDynamicSharedMemorySize, SMEM_BYTES);

    // 0) transpose x -> xt (bc, t, d)
    transpose_kernel<<<dim3(32, 8, 32), dim3(32, 8)>>>(x, xt);

    // 1) QKV: (1024 x 768) = xt (1024,256) @ w_qkv^T + b; Q,K -> qk, V -> vt (transposed)
    hgemm<<<dim3(6, 8, 32), 256, SMEM_BYTES>>>(
        xt, w_qkv, qk, vt,
        256, 256, 256, 512,
        1024ll * 256, 0, 1024ll * 512,
        1.0f, b_qkv, nullptr, 0, 1);

    // 2) scores = scale * Q @ K^T, mask -> -inf
    hgemm<<<dim3(8, 8, 32), 256, SMEM_BYTES>>>(
        qk, qk + 256, scores, nullptr,
        256, 512, 512, 1024,
        1024ll * 512, 1024ll * 512, 1024ll * 1024,
        0.0625f, nullptr, mask, 1024ll * 1024, 0);

    // 3) softmax
    softmax_kernel<<<32 * 1024, 256>>>(scores);

    // 4) attnO = P @ V   (V^T is (d, t), k-contiguous rows for B)
    hgemm<<<dim3(2, 8, 32), 256, SMEM_BYTES>>>(
        scores, vt, attnO, nullptr,
        1024, 1024, 1024, 256,
        1024ll * 1024, 256ll * 1024, 1024ll * 256,
        1.0f, nullptr, nullptr, 0, 0);

    // 5) out = attnO @ w_out^T + b_out
    hgemm<<<dim3(2, 8, 32), 256, SMEM_BYTES>>>(
        attnO, w_out, out, nullptr,
        256, 256, 256, 256,
        1024ll * 256, 0, 1024ll * 256,
        1.0f, b_out, nullptr, 0, 0);
}